// round 8
// baseline (speedup 1.0000x reference)
#include <cuda_runtime.h>

// Problem constants (fixed shapes: [16, 3, 512, 512] float32 inputs)
#define BATCH   16
#define CHN     3
#define IMG_H   512
#define IMG_W   512
#define KS      11
#define PADR    5
#define NWIN    (CHN * KS * KS)     // 363
#define TH_OUT  32                  // output rows per CTA (-> 256 CTAs, ~1 wave @ occ 2)
#define RCHUNK  8                   // rows staged in smem per sync batch
#define SEG     16                  // output pixels per thread in horizontal pass
#define THREADS 256
#define NCTAS   ((IMG_H / TH_OUT) * BATCH)   // 256

#define C1F 1.0e-4f                 // 0.01^2
#define C2F 9.0e-4f                 // 0.03^2
#define EPSF 1.0e-8f

// Skew keeping float PAIRS adjacent and 8B-aligned:
//   RSKW(2t+1) == RSKW(2t)+1 (2t even never carries into bit 5)
// Vertical 64-bit stores: conflict-free per 16-lane phase.
// Horizontal stride-16 scalar reads: near-conflict-free (worst 2-way, rare).
#define RSKW(x)  ((x) + 2 * ((x) >> 5))
#define VSW      544                // row stride in floats (>= RSKW(511)+1, even)

// Per-CTA partial sums: every slot written every run -> no zeroing pass, no atomics.
__device__ float g_partials[NCTAS];

// ---- f32x2 packed helpers (Blackwell; PTX-only, ptxas won't auto-fuse) ----
// "l" asm constraint binds a 64-bit INTEGER register: carry packed pairs as u64.
typedef unsigned long long f32x2_t;

__device__ __forceinline__ f32x2_t f2add(f32x2_t a, f32x2_t b) {
    f32x2_t r; asm("add.rn.f32x2 %0, %1, %2;" : "=l"(r) : "l"(a), "l"(b)); return r;
}
__device__ __forceinline__ f32x2_t f2mul(f32x2_t a, f32x2_t b) {
    f32x2_t r; asm("mul.rn.f32x2 %0, %1, %2;" : "=l"(r) : "l"(a), "l"(b)); return r;
}
__device__ __forceinline__ f32x2_t f2fma(f32x2_t a, f32x2_t b, f32x2_t c) {
    f32x2_t r; asm("fma.rn.f32x2 %0, %1, %2, %3;" : "=l"(r) : "l"(a), "l"(b), "l"(c)); return r;
}
// packed {-1.f, -1.f}
#define NEG1 (0xBF800000BF800000ULL)

struct Six2 { f32x2_t a0, a1, a2, b0, b1, b2; };

// Load 6 column-pairs (3 pred + 3 gt channels) at (row yy, col pair x2).
// Out-of-bounds rows give zeros (0ULL == two packed 0.f).
__device__ __forceinline__ Six2 ld_row2(const float* __restrict__ pb,
                                        const float* __restrict__ gb,
                                        int yy, int x2)
{
    Six2 s = {0ULL, 0ULL, 0ULL, 0ULL, 0ULL, 0ULL};
    if (yy >= 0 && yy < IMG_H) {
        const int plane = IMG_H * IMG_W;
        int off = yy * IMG_W + x2;
        s.a0 = *reinterpret_cast<const f32x2_t*>(pb + off);
        s.a1 = *reinterpret_cast<const f32x2_t*>(pb + off + plane);
        s.a2 = *reinterpret_cast<const f32x2_t*>(pb + off + 2 * plane);
        s.b0 = *reinterpret_cast<const f32x2_t*>(gb + off);
        s.b1 = *reinterpret_cast<const f32x2_t*>(gb + off + plane);
        s.b2 = *reinterpret_cast<const f32x2_t*>(gb + off + 2 * plane);
    }
    return s;
}

// V += moments(s)   (packed, 15 f32x2 ops)
__device__ __forceinline__ void acc_add(const Six2& s, f32x2_t V[5])
{
    V[0] = f2add(V[0], f2add(s.a0, f2add(s.a1, s.a2)));
    V[1] = f2add(V[1], f2add(s.b0, f2add(s.b1, s.b2)));
    V[2] = f2fma(s.a2, s.a2, f2fma(s.a1, s.a1, f2fma(s.a0, s.a0, V[2])));
    V[3] = f2fma(s.b2, s.b2, f2fma(s.b1, s.b1, f2fma(s.b0, s.b0, V[3])));
    V[4] = f2fma(s.a2, s.b2, f2fma(s.a1, s.b1, f2fma(s.a0, s.b0, V[4])));
}

// V -= moments(s)   (packed, 20 f32x2 ops; fma-with-(-1) avoids needing sub.f32x2)
__device__ __forceinline__ void acc_sub(const Six2& s, f32x2_t V[5])
{
    f32x2_t ta = f2add(s.a0, f2add(s.a1, s.a2));
    f32x2_t tb = f2add(s.b0, f2add(s.b1, s.b2));
    V[0] = f2fma(ta, NEG1, V[0]);
    V[1] = f2fma(tb, NEG1, V[1]);
    f32x2_t qa = f2fma(s.a2, s.a2, f2fma(s.a1, s.a1, f2mul(s.a0, s.a0)));
    f32x2_t qb = f2fma(s.b2, s.b2, f2fma(s.b1, s.b1, f2mul(s.b0, s.b0)));
    f32x2_t qc = f2fma(s.a2, s.b2, f2fma(s.a1, s.b1, f2mul(s.a0, s.b0)));
    V[2] = f2fma(qa, NEG1, V[2]);
    V[3] = f2fma(qb, NEG1, V[3]);
    V[4] = f2fma(qc, NEG1, V[4]);
}

__global__ __launch_bounds__(THREADS, 2)
void ssim_fused_kernel(const float* __restrict__ pred, const float* __restrict__ gt)
{
    extern __shared__ float vs[];   // [5 planes][RCHUNK rows][VSW floats]
    __shared__ float red[THREADS / 32];

    const int b  = blockIdx.y;
    const int y0 = blockIdx.x * TH_OUT;
    const int x2 = 2 * threadIdx.x;     // column pair owned in vertical pass

    const float* pb = pred + (size_t)b * CHN * IMG_H * IMG_W;
    const float* gb = gt   + (size_t)b * CHN * IMG_H * IMG_W;

    // ---- vertical warm-up: window sum over rows [y0-5, y0+4] ----
    f32x2_t V[5] = {0ULL, 0ULL, 0ULL, 0ULL, 0ULL};
    for (int yy = y0 - PADR; yy < y0 + PADR; ++yy) {
        Six2 s = ld_row2(pb, gb, yy, x2);
        acc_add(s, V);
    }

    // horizontal-phase thread remap: hr = row in chunk (0..7), lane g -> 16-px segment
    const int hr = threadIdx.x >> 5;
    const int g  = threadIdx.x & 31;
    const int xs = g * SEG;

    const float invN  = 1.0f / (float)NWIN;
    const float invN1 = 1.0f / (float)(NWIN - 1);

    float acc = 0.0f;

    for (int c = 0; c < TH_OUT / RCHUNK; ++c) {
        // ---- vertical pass: produce RCHUNK rows of windowed vertical sums ----
        #pragma unroll
        for (int r = 0; r < RCHUNK; ++r) {
            int y = y0 + c * RCHUNK + r;
            Six2 top = ld_row2(pb, gb, y + PADR, x2);   // enters window (batched loads)
            Six2 bot = ld_row2(pb, gb, y - PADR, x2);   // leaves window (for next row)
            acc_add(top, V);                            // window now [y-5, y+5]
            #pragma unroll
            for (int pl = 0; pl < 5; ++pl)
                *reinterpret_cast<f32x2_t*>(&vs[(pl * RCHUNK + r) * VSW + RSKW(x2)]) = V[pl];
            acc_sub(bot, V);                            // slide for next row
        }
        __syncthreads();

        // ---- horizontal pass over the RCHUNK staged rows (scalar) ----
        {
            const int rb = hr;
            float h[5];
            #pragma unroll
            for (int pl = 0; pl < 5; ++pl) {
                float s = 0.f;
                #pragma unroll
                for (int dx = -PADR; dx <= PADR; ++dx) {
                    int xx = xs + dx;
                    if (xx >= 0 && xx < IMG_W)
                        s += vs[(pl * RCHUNK + rb) * VSW + RSKW(xx)];
                }
                h[pl] = s;
            }
            // Fold 8 per-pixel fractions into one (N, D); 2 groups of 8 per segment.
            // (16-fold could underflow: den_min^16 could drop below FLT_MIN.)
            float Nf = 0.0f, Df = 1.0f;
            #pragma unroll
            for (int j = 0; j < SEG; ++j) {
                float mu_p  = h[0] * invN;
                float mu_g  = h[1] * invN;
                float var_p = (h[2] - h[0] * mu_p) * invN1;
                float var_g = (h[3] - h[1] * mu_g) * invN1;
                float cov   = (h[4] - h[0] * mu_g) * invN;
                float num = (2.0f * mu_p * mu_g + C1F) * (2.0f * cov + C2F);
                float den = (mu_p * mu_p + mu_g * mu_g + C1F) * (var_p + var_g + C2F) + EPSF;
                Nf = Nf * den + num * Df;
                Df = Df * den;
                if (j == 7) {               // flush first 8-group
                    acc += __fdividef(Nf, Df);
                    Nf = 0.0f; Df = 1.0f;
                }
                if (j < SEG - 1) {
                    int xx = xs + j;
                    int xa = xx + PADR + 1;   // enters window
                    int xr = xx - PADR;       // leaves window
                    #pragma unroll
                    for (int pl = 0; pl < 5; ++pl) {
                        float addv = (xa < IMG_W) ? vs[(pl * RCHUNK + rb) * VSW + RSKW(xa)] : 0.f;
                        float subv = (xr >= 0)    ? vs[(pl * RCHUNK + rb) * VSW + RSKW(xr)] : 0.f;
                        h[pl] += addv - subv;
                    }
                }
            }
            acc += __fdividef(Nf, Df);       // flush second 8-group
        }
        __syncthreads();
    }

    // ---- block reduction -> one partial per CTA ----
    #pragma unroll
    for (int o = 16; o > 0; o >>= 1)
        acc += __shfl_xor_sync(0xffffffffu, acc, o);
    if ((threadIdx.x & 31) == 0)
        red[threadIdx.x >> 5] = acc;
    __syncthreads();
    if (threadIdx.x < THREADS / 32) {
        float v = red[threadIdx.x];
        #pragma unroll
        for (int o = (THREADS / 64); o > 0; o >>= 1)
            v += __shfl_xor_sync(0xffu, v, o);
        if (threadIdx.x == 0)
            g_partials[blockIdx.y * gridDim.x + blockIdx.x] = v;
    }
}

__global__ __launch_bounds__(NCTAS)
void finalize_kernel(float* __restrict__ out)
{
    __shared__ double red[NCTAS / 32];
    double v = (double)g_partials[threadIdx.x];
    #pragma unroll
    for (int o = 16; o > 0; o >>= 1)
        v += __shfl_xor_sync(0xffffffffu, v, o);
    if ((threadIdx.x & 31) == 0)
        red[threadIdx.x >> 5] = v;
    __syncthreads();
    if (threadIdx.x == 0) {
        double s = 0.0;
        #pragma unroll
        for (int i = 0; i < NCTAS / 32; ++i)
            s += red[i];
        out[0] = 1.0f - (float)(s / (double)((size_t)BATCH * IMG_H * IMG_W));
    }
}

extern "C" void kernel_launch(void* const* d_in, const int* in_sizes, int n_in,
                              void* d_out, int out_size)
{
    const float* pred = (const float*)d_in[0];
    const float* gt   = (const float*)d_in[1];
    float* out = (float*)d_out;

    size_t smem = (size_t)5 * RCHUNK * VSW * sizeof(float);   // 87,040 B
    cudaFuncSetAttribute(ssim_fused_kernel,
                         cudaFuncAttributeMaxDynamicSharedMemorySize, (int)smem);

    dim3 grid(IMG_H / TH_OUT, BATCH);   // (16, 16) = 256 CTAs
    ssim_fused_kernel<<<grid, THREADS, smem>>>(pred, gt);
    finalize_kernel<<<1, NCTAS>>>(out);
}

// round 12
// speedup vs baseline: 1.0077x; 1.0077x over previous
#include <cuda_runtime.h>

// Problem constants (fixed shapes: [16, 3, 512, 512] float32 inputs)
#define BATCH   16
#define CHN     3
#define IMG_H   512
#define IMG_W   512
#define KS      11
#define PADR    5
#define NWIN    (CHN * KS * KS)     // 363
#define TH_OUT  32                  // output rows per CTA (-> 256 CTAs, ~1 wave @ occ 2)
#define RCHUNK  8                   // rows staged in smem per sync batch
#define SEG     16                  // output pixels per thread in horizontal pass
#define THREADS 256
#define NCTAS   ((IMG_H / TH_OUT) * BATCH)   // 256

#define C1F 1.0e-4f                 // 0.01^2
#define C2F 9.0e-4f                 // 0.03^2
#define EPSF 1.0e-8f

// Skew keeping float PAIRS adjacent and 8B-aligned:
//   RSKW(2t+1) == RSKW(2t)+1 (2t even never carries into bit 5)
#define RSKW(x)  ((x) + 2 * ((x) >> 5))
#define VSW      544                // row stride in floats (>= RSKW(511)+1, even)

// Per-CTA partial sums + arrival counter (self-resetting -> graph-replay safe).
__device__ float g_partials[NCTAS];
__device__ unsigned int g_arrived;   // zero-initialized at module load; last CTA resets to 0

// ---- f32x2 packed helpers (Blackwell; PTX-only, ptxas won't auto-fuse) ----
// "l" asm constraint binds a 64-bit INTEGER register: carry packed pairs as u64.
typedef unsigned long long f32x2_t;

__device__ __forceinline__ f32x2_t f2add(f32x2_t a, f32x2_t b) {
    f32x2_t r; asm("add.rn.f32x2 %0, %1, %2;" : "=l"(r) : "l"(a), "l"(b)); return r;
}
__device__ __forceinline__ f32x2_t f2mul(f32x2_t a, f32x2_t b) {
    f32x2_t r; asm("mul.rn.f32x2 %0, %1, %2;" : "=l"(r) : "l"(a), "l"(b)); return r;
}
__device__ __forceinline__ f32x2_t f2fma(f32x2_t a, f32x2_t b, f32x2_t c) {
    f32x2_t r; asm("fma.rn.f32x2 %0, %1, %2, %3;" : "=l"(r) : "l"(a), "l"(b), "l"(c)); return r;
}
// packed {-1.f, -1.f}
#define NEG1 (0xBF800000BF800000ULL)

struct Six2 { f32x2_t a0, a1, a2, b0, b1, b2; };

// Load 6 column-pairs (3 pred + 3 gt channels) at (row yy, col pair x2).
// Out-of-bounds rows give zeros (0ULL == two packed 0.f).
__device__ __forceinline__ Six2 ld_row2(const float* __restrict__ pb,
                                        const float* __restrict__ gb,
                                        int yy, int x2)
{
    Six2 s = {0ULL, 0ULL, 0ULL, 0ULL, 0ULL, 0ULL};
    if (yy >= 0 && yy < IMG_H) {
        const int plane = IMG_H * IMG_W;
        int off = yy * IMG_W + x2;
        s.a0 = *reinterpret_cast<const f32x2_t*>(pb + off);
        s.a1 = *reinterpret_cast<const f32x2_t*>(pb + off + plane);
        s.a2 = *reinterpret_cast<const f32x2_t*>(pb + off + 2 * plane);
        s.b0 = *reinterpret_cast<const f32x2_t*>(gb + off);
        s.b1 = *reinterpret_cast<const f32x2_t*>(gb + off + plane);
        s.b2 = *reinterpret_cast<const f32x2_t*>(gb + off + 2 * plane);
    }
    return s;
}

// V += moments(s)   (packed, 15 f32x2 ops)
__device__ __forceinline__ void acc_add(const Six2& s, f32x2_t V[5])
{
    V[0] = f2add(V[0], f2add(s.a0, f2add(s.a1, s.a2)));
    V[1] = f2add(V[1], f2add(s.b0, f2add(s.b1, s.b2)));
    V[2] = f2fma(s.a2, s.a2, f2fma(s.a1, s.a1, f2fma(s.a0, s.a0, V[2])));
    V[3] = f2fma(s.b2, s.b2, f2fma(s.b1, s.b1, f2fma(s.b0, s.b0, V[3])));
    V[4] = f2fma(s.a2, s.b2, f2fma(s.a1, s.b1, f2fma(s.a0, s.b0, V[4])));
}

// V -= moments(s)   (packed, 20 f32x2 ops; fma-with-(-1) avoids needing sub.f32x2)
__device__ __forceinline__ void acc_sub(const Six2& s, f32x2_t V[5])
{
    f32x2_t ta = f2add(s.a0, f2add(s.a1, s.a2));
    f32x2_t tb = f2add(s.b0, f2add(s.b1, s.b2));
    V[0] = f2fma(ta, NEG1, V[0]);
    V[1] = f2fma(tb, NEG1, V[1]);
    f32x2_t qa = f2fma(s.a2, s.a2, f2fma(s.a1, s.a1, f2mul(s.a0, s.a0)));
    f32x2_t qb = f2fma(s.b2, s.b2, f2fma(s.b1, s.b1, f2mul(s.b0, s.b0)));
    f32x2_t qc = f2fma(s.a2, s.b2, f2fma(s.a1, s.b1, f2mul(s.a0, s.b0)));
    V[2] = f2fma(qa, NEG1, V[2]);
    V[3] = f2fma(qb, NEG1, V[3]);
    V[4] = f2fma(qc, NEG1, V[4]);
}

__global__ __launch_bounds__(THREADS, 2)
void ssim_fused_kernel(const float* __restrict__ pred, const float* __restrict__ gt,
                       float* __restrict__ out)
{
    extern __shared__ float vs[];   // [5 planes][RCHUNK rows][VSW floats]
    __shared__ float red[THREADS / 32];
    __shared__ unsigned int s_rank;

    const int b  = blockIdx.y;
    const int y0 = blockIdx.x * TH_OUT;
    const int x2 = 2 * threadIdx.x;     // column pair owned in vertical pass

    const float* pb = pred + (size_t)b * CHN * IMG_H * IMG_W;
    const float* gb = gt   + (size_t)b * CHN * IMG_H * IMG_W;

    // ---- vertical warm-up: window sum over rows [y0-5, y0+4] ----
    f32x2_t V[5] = {0ULL, 0ULL, 0ULL, 0ULL, 0ULL};
    for (int yy = y0 - PADR; yy < y0 + PADR; ++yy) {
        Six2 s = ld_row2(pb, gb, yy, x2);
        acc_add(s, V);
    }

    // horizontal-phase thread remap: hr = row in chunk (0..7), lane g -> 16-px segment
    const int hr = threadIdx.x >> 5;
    const int g  = threadIdx.x & 31;
    const int xs = g * SEG;

    const float invN  = 1.0f / (float)NWIN;
    const float invN1 = 1.0f / (float)(NWIN - 1);

    float acc = 0.0f;

    for (int c = 0; c < TH_OUT / RCHUNK; ++c) {
        // ---- vertical pass: produce RCHUNK rows of windowed vertical sums ----
        #pragma unroll
        for (int r = 0; r < RCHUNK; ++r) {
            int y = y0 + c * RCHUNK + r;
            Six2 top = ld_row2(pb, gb, y + PADR, x2);   // enters window (batched loads)
            Six2 bot = ld_row2(pb, gb, y - PADR, x2);   // leaves window (for next row)
            acc_add(top, V);                            // window now [y-5, y+5]
            #pragma unroll
            for (int pl = 0; pl < 5; ++pl)
                *reinterpret_cast<f32x2_t*>(&vs[(pl * RCHUNK + r) * VSW + RSKW(x2)]) = V[pl];
            acc_sub(bot, V);                            // slide for next row
        }
        __syncthreads();

        // ---- horizontal pass over the RCHUNK staged rows (scalar) ----
        {
            const int rb = hr;
            float h[5];
            #pragma unroll
            for (int pl = 0; pl < 5; ++pl) {
                float s = 0.f;
                #pragma unroll
                for (int dx = -PADR; dx <= PADR; ++dx) {
                    int xx = xs + dx;
                    if (xx >= 0 && xx < IMG_W)
                        s += vs[(pl * RCHUNK + rb) * VSW + RSKW(xx)];
                }
                h[pl] = s;
            }
            // Fold 8 per-pixel fractions into one (N, D); 2 groups of 8 per segment.
            float Nf = 0.0f, Df = 1.0f;
            #pragma unroll
            for (int j = 0; j < SEG; ++j) {
                float mu_p  = h[0] * invN;
                float mu_g  = h[1] * invN;
                float var_p = (h[2] - h[0] * mu_p) * invN1;
                float var_g = (h[3] - h[1] * mu_g) * invN1;
                float cov   = (h[4] - h[0] * mu_g) * invN;
                float num = (2.0f * mu_p * mu_g + C1F) * (2.0f * cov + C2F);
                float den = (mu_p * mu_p + mu_g * mu_g + C1F) * (var_p + var_g + C2F) + EPSF;
                Nf = Nf * den + num * Df;
                Df = Df * den;
                if (j == 7) {               // flush first 8-group
                    acc += __fdividef(Nf, Df);
                    Nf = 0.0f; Df = 1.0f;
                }
                if (j < SEG - 1) {
                    int xx = xs + j;
                    int xa = xx + PADR + 1;   // enters window
                    int xr = xx - PADR;       // leaves window
                    #pragma unroll
                    for (int pl = 0; pl < 5; ++pl) {
                        float addv = (xa < IMG_W) ? vs[(pl * RCHUNK + rb) * VSW + RSKW(xa)] : 0.f;
                        float subv = (xr >= 0)    ? vs[(pl * RCHUNK + rb) * VSW + RSKW(xr)] : 0.f;
                        h[pl] += addv - subv;
                    }
                }
            }
            acc += __fdividef(Nf, Df);       // flush second 8-group
        }
        __syncthreads();
    }

    // ---- block reduction -> one partial per CTA ----
    #pragma unroll
    for (int o = 16; o > 0; o >>= 1)
        acc += __shfl_xor_sync(0xffffffffu, acc, o);
    if ((threadIdx.x & 31) == 0)
        red[threadIdx.x >> 5] = acc;
    __syncthreads();
    if (threadIdx.x == 0) {
        float v = 0.f;
        #pragma unroll
        for (int i = 0; i < THREADS / 32; ++i)
            v += red[i];
        g_partials[blockIdx.y * gridDim.x + blockIdx.x] = v;
        __threadfence();                              // partial visible before arrival
        unsigned int rank = atomicAdd(&g_arrived, 1u);
        s_rank = rank;
    }
    __syncthreads();

    // ---- last CTA to arrive does the final reduction (fixed-order -> deterministic) ----
    if (s_rank == NCTAS - 1) {
        // NCTAS == THREADS: one partial per thread
        double v = (double)((volatile float*)g_partials)[threadIdx.x];
        #pragma unroll
        for (int o = 16; o > 0; o >>= 1)
            v += __shfl_xor_sync(0xffffffffu, v, o);
        __shared__ double dred[THREADS / 32];
        if ((threadIdx.x & 31) == 0)
            dred[threadIdx.x >> 5] = v;
        __syncthreads();
        if (threadIdx.x == 0) {
            double s = 0.0;
            #pragma unroll
            for (int i = 0; i < THREADS / 32; ++i)
                s += dred[i];
            out[0] = 1.0f - (float)(s / (double)((size_t)BATCH * IMG_H * IMG_W));
            g_arrived = 0;                            // reset for next graph replay
        }
    }
}

extern "C" void kernel_launch(void* const* d_in, const int* in_sizes, int n_in,
                              void* d_out, int out_size)
{
    const float* pred = (const float*)d_in[0];
    const float* gt   = (const float*)d_in[1];
    float* out = (float*)d_out;

    size_t smem = (size_t)5 * RCHUNK * VSW * sizeof(float);   // 87,040 B
    cudaFuncSetAttribute(ssim_fused_kernel,
                         cudaFuncAttributeMaxDynamicSharedMemorySize, (int)smem);

    dim3 grid(IMG_H / TH_OUT, BATCH);   // (16, 16) = 256 CTAs
    ssim_fused_kernel<<<grid, THREADS, smem>>>(pred, gt, out);
}